// round 2
// baseline (speedup 1.0000x reference)
#include <cuda_runtime.h>
#include <stdint.h>

#define TP   64    // points per block
#define NTH  256
#define WDIM 128
#define HDIM 64
#define EXP  8
#define DXX  63
#define DVV  27

// ---- shared memory layout (floats) ----
#define OFF_XYZH 0                        // [64][66]: xyz PE (phases A,B), reused as h (C3,C4)
#define OFF_VD   (OFF_XYZH + 64*66)       // [64][28]
#define OFF_Y    (OFF_VD   + 64*28)       // [64][128]
#define OFF_SH   (OFF_Y    + 64*128)      // [64][132]  (padded stride vs bank conflicts)
#define OFF_G    (OFF_SH   + 64*132)      // [64][8]
#define OFF_SC   (OFF_G    + 64*8)        // [64]
#define OFF_SIG  (OFF_SC   + 64)          // [64]
#define OFF_RGB  (OFF_SIG  + 64)          // [64][3]
#define OFF_BEST (OFF_RGB  + 64*3)        // [64][5]: score, sigma, r, g, b
#define OFF_RED  (OFF_BEST + 64*5)        // [4][64]
#define SMEM_FLOATS (OFF_RED + 64*4)      // 24064 floats = 96256 bytes

// ---- JAX threefry2x32 (20 rounds) ----
__device__ __forceinline__ uint2 tf2x32(unsigned k0, unsigned k1, unsigned x0, unsigned x1) {
    unsigned ks2 = k0 ^ k1 ^ 0x1BD11BDAu;
    x0 += k0; x1 += k1;
#define TFR(r) { x0 += x1; x1 = (x1 << (r)) | (x1 >> (32 - (r))); x1 ^= x0; }
    TFR(13) TFR(15) TFR(26) TFR(6)
    x0 += k1;  x1 += ks2 + 1u;
    TFR(17) TFR(29) TFR(16) TFR(24)
    x0 += ks2; x1 += k0 + 2u;
    TFR(13) TFR(15) TFR(26) TFR(6)
    x0 += k0;  x1 += k1 + 3u;
    TFR(17) TFR(29) TFR(16) TFR(24)
    x0 += k1;  x1 += ks2 + 4u;
    TFR(13) TFR(15) TFR(26) TFR(6)
    x0 += ks2; x1 += k0 + 5u;
#undef TFR
    return make_uint2(x0, x1);
}

__global__ void __launch_bounds__(NTH)
nerf_fused(const float* __restrict__ x,
           const float* __restrict__ W_enc, const float* __restrict__ b_enc,
           const float* __restrict__ W_sh,  const float* __restrict__ b_sh,
           const float* __restrict__ w_sig, const float* __restrict__ b_sig,
           const float* __restrict__ W_r1,  const float* __restrict__ b_r1,
           const float* __restrict__ W_r2,  const float* __restrict__ b_r2,
           float* __restrict__ out, int n)
{
    extern __shared__ float sm[];
    const int tid = threadIdx.x;
    const int n0  = blockIdx.x * TP;

    float* s_xyz  = sm + OFF_XYZH;   // stride 66
    float* s_h    = sm + OFF_XYZH;   // stride 66 (overlay; xyz dead after phase B)
    float* s_vd   = sm + OFF_VD;     // stride 28
    float* s_y    = sm + OFF_Y;      // stride 128
    float* s_sh   = sm + OFF_SH;     // stride 132
    float* s_g    = sm + OFF_G;
    float* s_sc   = sm + OFF_SC;
    float* s_sig  = sm + OFF_SIG;
    float* s_rgb  = sm + OFF_RGB;
    float* s_best = sm + OFF_BEST;
    float* s_red  = sm + OFF_RED;

    // ---------- Phase A: positional encodings ----------
    if (tid < 192) {
        const int p = tid / 3, c = tid % 3;
        float xc = 0.f, vc = 0.f;
        if (n0 + p < n) {
            xc = x[(n0 + p) * 6 + c];
            vc = x[(n0 + p) * 6 + 3 + c];
        }
        s_xyz[p * 66 + c] = xc;
        float f = 1.f;
#pragma unroll
        for (int i = 0; i < 10; i++) {
            float sv, cv; sincosf(f * xc, &sv, &cv);
            s_xyz[p * 66 + 3  + 3 * i + c] = sv;
            s_xyz[p * 66 + 33 + 3 * i + c] = cv;
            f *= 2.f;
        }
        s_vd[p * 28 + c] = vc;
        f = 1.f;
#pragma unroll
        for (int i = 0; i < 4; i++) {
            float sv, cv; sincosf(f * vc, &sv, &cv);
            s_vd[p * 28 + 3  + 3 * i + c] = sv;
            s_vd[p * 28 + 15 + 3 * i + c] = cv;
            f *= 2.f;
        }
    }
    // ---------- Phase A2: Gumbel noise via JAX threefry (PARTITIONABLE path) ----------
    // jax_threefry_partitionable=True (current default): per-element 64-bit
    // counter f, inputs (hi(f), lo(f)) = (0, f); 32-bit output = out0 ^ out1.
    {
        for (int idx = tid; idx < TP * EXP; idx += NTH) {
            const int p = idx >> 3;
            const unsigned f = (unsigned)(n0 + p) * 8u + (unsigned)(idx & 7);
            const uint2 r = tf2x32(0u, 42u, 0u, f);
            const unsigned bits = r.x ^ r.y;
            const float u = __uint_as_float((bits >> 9) | 0x3f800000u) - 1.0f;
            s_g[idx] = -logf(-logf(u + 1e-20f) + 1e-20f);
        }
    }
    __syncthreads();

    // ---------- Phase B: y = relu(xyz_pe @ W_enc + b_enc) ----------
    {
        const int wp = tid >> 5, l = tid & 31, p0 = wp * 8;
        float acc[8][4];
        const float4 bv = *(const float4*)(b_enc + l * 4);
#pragma unroll
        for (int p = 0; p < 8; p++) { acc[p][0] = bv.x; acc[p][1] = bv.y; acc[p][2] = bv.z; acc[p][3] = bv.w; }
        const float* xb = s_xyz + p0 * 66;
#pragma unroll 3
        for (int k = 0; k < DXX; k++) {
            const float4 wv = *(const float4*)(W_enc + k * WDIM + l * 4);
#pragma unroll
            for (int p = 0; p < 8; p++) {
                const float xv = xb[p * 66 + k];
                acc[p][0] = fmaf(xv, wv.x, acc[p][0]);
                acc[p][1] = fmaf(xv, wv.y, acc[p][1]);
                acc[p][2] = fmaf(xv, wv.z, acc[p][2]);
                acc[p][3] = fmaf(xv, wv.w, acc[p][3]);
            }
        }
#pragma unroll
        for (int p = 0; p < 8; p++) {
            float4 r4;
            r4.x = fmaxf(acc[p][0], 0.f); r4.y = fmaxf(acc[p][1], 0.f);
            r4.z = fmaxf(acc[p][2], 0.f); r4.w = fmaxf(acc[p][3], 0.f);
            *(float4*)(s_y + (p0 + p) * WDIM + l * 4) = r4;
        }
    }
    __syncthreads();

    // ---------- Expert loop ----------
    for (int e = 0; e < EXP; e++) {
        // C1: shape = relu(y @ W_sh[e] + b_sh[e])
        {
            const int wp = tid >> 5, l = tid & 31, p0 = wp * 8;
            float acc[8][4];
            const float4 bv = *(const float4*)(b_sh + e * WDIM + l * 4);
#pragma unroll
            for (int p = 0; p < 8; p++) { acc[p][0] = bv.x; acc[p][1] = bv.y; acc[p][2] = bv.z; acc[p][3] = bv.w; }
            const float* wb = W_sh + e * WDIM * WDIM + l * 4;
            const float* yb = s_y + p0 * WDIM;
#pragma unroll 4
            for (int k = 0; k < WDIM; k++) {
                const float4 wv = *(const float4*)(wb + k * WDIM);
#pragma unroll
                for (int p = 0; p < 8; p++) {
                    const float yv = yb[p * WDIM + k];
                    acc[p][0] = fmaf(yv, wv.x, acc[p][0]);
                    acc[p][1] = fmaf(yv, wv.y, acc[p][1]);
                    acc[p][2] = fmaf(yv, wv.z, acc[p][2]);
                    acc[p][3] = fmaf(yv, wv.w, acc[p][3]);
                }
            }
#pragma unroll
            for (int p = 0; p < 8; p++) {
                float4 r4;
                r4.x = fmaxf(acc[p][0], 0.f); r4.y = fmaxf(acc[p][1], 0.f);
                r4.z = fmaxf(acc[p][2], 0.f); r4.w = fmaxf(acc[p][3], 0.f);
                *(float4*)(s_sh + (p0 + p) * 132 + l * 4) = r4;
            }
        }
        __syncthreads();

        // C2: sigma partials: shape . w_sig (4 threads/point)
        {
            const int p = tid & 63, q = tid >> 6;
            const float* sp = s_sh + p * 132 + q * 32;
            const float* wq = w_sig + q * 32;
            float acc = 0.f;
#pragma unroll
            for (int i = 0; i < 32; i++) acc = fmaf(sp[i], wq[i], acc);
            s_red[q * 64 + p] = acc;
        }
        __syncthreads();
        if (tid < 64) {
            const int p = tid;
            const float t = s_red[p] + s_red[64 + p] + s_red[128 + p] + s_red[192 + p] + b_sig[0];
            const float sg = fmaxf(t, 0.f) + log1pf(expf(-fabsf(t)));  // softplus
            s_sig[p] = sg;
            s_sc[p] = logf(sg + 1e-10f) / 0.166667f + s_g[p * 8 + e];
        }

        // C3: h = relu([shape | vd] @ W_r1[e] + b_r1[e])
        {
            const int wp = tid >> 5, l = tid & 31, p0 = wp * 8;
            float acc[8][2];
            const float2 bv = *(const float2*)(b_r1 + e * HDIM + l * 2);
#pragma unroll
            for (int p = 0; p < 8; p++) { acc[p][0] = bv.x; acc[p][1] = bv.y; }
            const float* w1 = W_r1 + e * (WDIM + DVV) * HDIM + l * 2;
            const float* sb = s_sh + p0 * 132;
#pragma unroll 4
            for (int k = 0; k < WDIM; k++) {
                const float2 wv = *(const float2*)(w1 + k * HDIM);
#pragma unroll
                for (int p = 0; p < 8; p++) {
                    const float xv = sb[p * 132 + k];
                    acc[p][0] = fmaf(xv, wv.x, acc[p][0]);
                    acc[p][1] = fmaf(xv, wv.y, acc[p][1]);
                }
            }
            const float* vb = s_vd + p0 * 28;
#pragma unroll
            for (int k = 0; k < DVV; k++) {
                const float2 wv = *(const float2*)(w1 + (WDIM + k) * HDIM);
#pragma unroll
                for (int p = 0; p < 8; p++) {
                    const float xv = vb[p * 28 + k];
                    acc[p][0] = fmaf(xv, wv.x, acc[p][0]);
                    acc[p][1] = fmaf(xv, wv.y, acc[p][1]);
                }
            }
#pragma unroll
            for (int p = 0; p < 8; p++) {
                float2 r2;
                r2.x = fmaxf(acc[p][0], 0.f);
                r2.y = fmaxf(acc[p][1], 0.f);
                *(float2*)(s_h + (p0 + p) * 66 + l * 2) = r2;
            }
        }
        __syncthreads();

        // C4: rgb = sigmoid(h @ W_r2[e] + b_r2[e])
        if (tid < 192) {
            const int p = tid % 64, c = tid / 64;
            float acc = b_r2[e * 3 + c];
            const float* hp = s_h + p * 66;
            const float* w2 = W_r2 + e * HDIM * 3 + c;
#pragma unroll
            for (int k = 0; k < HDIM; k++) acc = fmaf(hp[k], w2[k * 3], acc);
            s_rgb[p * 3 + c] = 1.f / (1.f + expf(-acc));
        }
        __syncthreads();

        // C5: running argmax (first-max-wins, matching jnp.argmax)
        if (tid < 64) {
            const int p = tid;
            const float sc = s_sc[p];
            if (e == 0 || sc > s_best[p * 5]) {
                s_best[p * 5]     = sc;
                s_best[p * 5 + 1] = s_sig[p];
                s_best[p * 5 + 2] = s_rgb[p * 3];
                s_best[p * 5 + 3] = s_rgb[p * 3 + 1];
                s_best[p * 5 + 4] = s_rgb[p * 3 + 2];
            }
        }
        __syncthreads();
    }

    // ---------- output: [rgb, sigma_pooled] ----------
    {
        const int p = tid >> 2, c = tid & 3;
        if (n0 + p < n)
            out[(n0 + p) * 4 + c] = (c < 3) ? s_best[p * 5 + 2 + c] : s_best[p * 5 + 1];
    }
}

extern "C" void kernel_launch(void* const* d_in, const int* in_sizes, int n_in,
                              void* d_out, int out_size) {
    const float* x     = (const float*)d_in[0];
    const float* W_enc = (const float*)d_in[1];
    const float* b_enc = (const float*)d_in[2];
    const float* W_sh  = (const float*)d_in[3];
    const float* b_sh  = (const float*)d_in[4];
    const float* w_sig = (const float*)d_in[5];
    const float* b_sig = (const float*)d_in[6];
    const float* W_r1  = (const float*)d_in[7];
    const float* b_r1  = (const float*)d_in[8];
    const float* W_r2  = (const float*)d_in[9];
    const float* b_r2  = (const float*)d_in[10];
    float* out = (float*)d_out;

    const int n = in_sizes[0] / 6;
    const int blocks = (n + TP - 1) / TP;
    const int smem = SMEM_FLOATS * (int)sizeof(float);

    cudaFuncSetAttribute(nerf_fused, cudaFuncAttributeMaxDynamicSharedMemorySize, smem);
    nerf_fused<<<blocks, NTH, smem>>>(x, W_enc, b_enc, W_sh, b_sh, w_sig, b_sig,
                                      W_r1, b_r1, W_r2, b_r2, out, n);
}

// round 3
// speedup vs baseline: 1.1211x; 1.1211x over previous
#include <cuda_runtime.h>
#include <stdint.h>

#define TP   64
#define NTH  256
#define WDIM 128
#define HDIM 64
#define EXP  8
#define DXX  63
#define DVV  27

typedef unsigned long long ull;

// ---- shared memory layout (floats) ----
#define OFF_XYZH 0                         // [64][66] xyz PE; reused as h after expert loop
#define OFF_VD   (OFF_XYZH + 64*66)        // [64][28]
#define OFF_Y    (OFF_VD   + 64*28)        // [64][128]
#define OFF_SH   (OFF_Y    + 64*128)       // [64][132]
#define OFF_G    (OFF_SH   + 64*132)       // [64][8]
#define OFF_RED  (OFF_G    + 64*8)         // [4][64]
#define OFF_BSC  (OFF_RED  + 64*4)         // [64] best score
#define OFF_BSIG (OFF_BSC  + 64)           // [64] best sigma
#define OFF_BEXP (OFF_BSIG + 64)           // [64] best expert (as float)
#define SMEM_FLOATS (OFF_BEXP + 64)

// ---- packed f32x2 helpers ----
__device__ __forceinline__ ull pack2(float a, float b) {
    ull r; asm("mov.b64 %0, {%1, %2};" : "=l"(r) : "f"(a), "f"(b)); return r;
}
__device__ __forceinline__ void ffma2(ull& acc, ull a, ull b) {
    asm("fma.rn.f32x2 %0, %1, %2, %0;" : "+l"(acc) : "l"(a), "l"(b));
}
__device__ __forceinline__ float2 unpack2(ull v) {
    float2 f; asm("mov.b64 {%0, %1}, %2;" : "=f"(f.x), "=f"(f.y) : "l"(v)); return f;
}

// ---- JAX threefry2x32 (20 rounds) ----
__device__ __forceinline__ uint2 tf2x32(unsigned k0, unsigned k1, unsigned x0, unsigned x1) {
    unsigned ks2 = k0 ^ k1 ^ 0x1BD11BDAu;
    x0 += k0; x1 += k1;
#define TFR(r) { x0 += x1; x1 = (x1 << (r)) | (x1 >> (32 - (r))); x1 ^= x0; }
    TFR(13) TFR(15) TFR(26) TFR(6)
    x0 += k1;  x1 += ks2 + 1u;
    TFR(17) TFR(29) TFR(16) TFR(24)
    x0 += ks2; x1 += k0 + 2u;
    TFR(13) TFR(15) TFR(26) TFR(6)
    x0 += k0;  x1 += k1 + 3u;
    TFR(17) TFR(29) TFR(16) TFR(24)
    x0 += k1;  x1 += ks2 + 4u;
    TFR(13) TFR(15) TFR(26) TFR(6)
    x0 += ks2; x1 += k0 + 5u;
#undef TFR
    return make_uint2(x0, x1);
}

__global__ void __launch_bounds__(NTH, 2)
nerf_fused(const float* __restrict__ x,
           const float* __restrict__ W_enc, const float* __restrict__ b_enc,
           const float* __restrict__ W_sh,  const float* __restrict__ b_sh,
           const float* __restrict__ w_sig, const float* __restrict__ b_sig,
           const float* __restrict__ W_r1,  const float* __restrict__ b_r1,
           const float* __restrict__ W_r2,  const float* __restrict__ b_r2,
           float* __restrict__ out, int n)
{
    extern __shared__ float sm[];
    const int tid = threadIdx.x;
    const int n0  = blockIdx.x * TP;

    float* s_xyz  = sm + OFF_XYZH;   // stride 66
    float* s_h    = sm + OFF_XYZH;   // overlay (xyz dead after Phase B)
    float* s_vd   = sm + OFF_VD;     // stride 28
    float* s_y    = sm + OFF_Y;      // stride 128
    float* s_sh   = sm + OFF_SH;     // stride 132
    float* s_g    = sm + OFF_G;
    float* s_red  = sm + OFF_RED;
    float* s_bsc  = sm + OFF_BSC;
    float* s_bsig = sm + OFF_BSIG;
    float* s_bexp = sm + OFF_BEXP;

    // ---------- Phase A: positional encodings ----------
    if (tid < 192) {
        const int p = tid / 3, c = tid % 3;
        float xc = 0.f, vc = 0.f;
        if (n0 + p < n) {
            xc = x[(n0 + p) * 6 + c];
            vc = x[(n0 + p) * 6 + 3 + c];
        }
        s_xyz[p * 66 + c] = xc;
        float f = 1.f;
#pragma unroll
        for (int i = 0; i < 10; i++) {
            float sv, cv; sincosf(f * xc, &sv, &cv);
            s_xyz[p * 66 + 3  + 3 * i + c] = sv;
            s_xyz[p * 66 + 33 + 3 * i + c] = cv;
            f *= 2.f;
        }
        s_vd[p * 28 + c] = vc;
        f = 1.f;
#pragma unroll
        for (int i = 0; i < 4; i++) {
            float sv, cv; sincosf(f * vc, &sv, &cv);
            s_vd[p * 28 + 3  + 3 * i + c] = sv;
            s_vd[p * 28 + 15 + 3 * i + c] = cv;
            f *= 2.f;
        }
        if (tid < 64) s_vd[tid * 28 + 27] = 0.f;  // pad for float2 k-tail
    }
    // ---------- Phase A2: Gumbel noise (JAX threefry, partitionable) ----------
    for (int idx = tid; idx < TP * EXP; idx += NTH) {
        const int p = idx >> 3;
        const unsigned f = (unsigned)(n0 + p) * 8u + (unsigned)(idx & 7);
        const uint2 r = tf2x32(0u, 42u, 0u, f);
        const unsigned bits = r.x ^ r.y;
        const float u = __uint_as_float((bits >> 9) | 0x3f800000u) - 1.0f;
        s_g[idx] = -logf(-logf(u + 1e-20f) + 1e-20f);
    }
    __syncthreads();

    const int wp = tid >> 5, l = tid & 31, p0 = wp * 8;

    // ---------- Phase B: y = relu(xyz_pe @ W_enc + b_enc), f32x2 k-packed ----------
    {
        ull acc[8][4];
#pragma unroll
        for (int p = 0; p < 8; p++)
#pragma unroll
            for (int c = 0; c < 4; c++) acc[p][c] = 0ull;
        const float* wb = W_enc + l * 4;
        const float* xb = s_xyz + p0 * 66;
#pragma unroll 2
        for (int k = 0; k < 62; k += 2) {
            const float4 w0 = *(const float4*)(wb + k * WDIM);
            const float4 w1 = *(const float4*)(wb + (k + 1) * WDIM);
            const ull pc0 = pack2(w0.x, w1.x), pc1 = pack2(w0.y, w1.y);
            const ull pc2 = pack2(w0.z, w1.z), pc3 = pack2(w0.w, w1.w);
#pragma unroll
            for (int p = 0; p < 8; p++) {
                const ull a = *(const ull*)(xb + p * 66 + k);
                ffma2(acc[p][0], a, pc0); ffma2(acc[p][1], a, pc1);
                ffma2(acc[p][2], a, pc2); ffma2(acc[p][3], a, pc3);
            }
        }
        {   // tail k = 62
            const float4 w0 = *(const float4*)(wb + 62 * WDIM);
            const ull pc0 = pack2(w0.x, 0.f), pc1 = pack2(w0.y, 0.f);
            const ull pc2 = pack2(w0.z, 0.f), pc3 = pack2(w0.w, 0.f);
#pragma unroll
            for (int p = 0; p < 8; p++) {
                const ull a = pack2(xb[p * 66 + 62], 0.f);
                ffma2(acc[p][0], a, pc0); ffma2(acc[p][1], a, pc1);
                ffma2(acc[p][2], a, pc2); ffma2(acc[p][3], a, pc3);
            }
        }
        const float4 bv = *(const float4*)(b_enc + l * 4);
#pragma unroll
        for (int p = 0; p < 8; p++) {
            const float2 f0 = unpack2(acc[p][0]), f1 = unpack2(acc[p][1]);
            const float2 f2 = unpack2(acc[p][2]), f3 = unpack2(acc[p][3]);
            float4 r4;
            r4.x = fmaxf(f0.x + f0.y + bv.x, 0.f);
            r4.y = fmaxf(f1.x + f1.y + bv.y, 0.f);
            r4.z = fmaxf(f2.x + f2.y + bv.z, 0.f);
            r4.w = fmaxf(f3.x + f3.y + bv.w, 0.f);
            *(float4*)(s_y + (p0 + p) * WDIM + l * 4) = r4;
        }
    }
    __syncthreads();

    // ---------- Expert loop: shape + sigma + gating score only ----------
    for (int e = 0; e < EXP; e++) {
        // C1: shape = relu(y @ W_sh[e] + b_sh[e]), f32x2 k-packed
        {
            ull acc[8][4];
#pragma unroll
            for (int p = 0; p < 8; p++)
#pragma unroll
                for (int c = 0; c < 4; c++) acc[p][c] = 0ull;
            const float* wb = W_sh + e * WDIM * WDIM + l * 4;
            const float* yb = s_y + p0 * WDIM;
#pragma unroll 2
            for (int k = 0; k < WDIM; k += 2) {
                const float4 w0 = *(const float4*)(wb + k * WDIM);
                const float4 w1 = *(const float4*)(wb + (k + 1) * WDIM);
                const ull pc0 = pack2(w0.x, w1.x), pc1 = pack2(w0.y, w1.y);
                const ull pc2 = pack2(w0.z, w1.z), pc3 = pack2(w0.w, w1.w);
#pragma unroll
                for (int p = 0; p < 8; p++) {
                    const ull a = *(const ull*)(yb + p * WDIM + k);
                    ffma2(acc[p][0], a, pc0); ffma2(acc[p][1], a, pc1);
                    ffma2(acc[p][2], a, pc2); ffma2(acc[p][3], a, pc3);
                }
            }
            const float4 bv = *(const float4*)(b_sh + e * WDIM + l * 4);
#pragma unroll
            for (int p = 0; p < 8; p++) {
                const float2 f0 = unpack2(acc[p][0]), f1 = unpack2(acc[p][1]);
                const float2 f2 = unpack2(acc[p][2]), f3 = unpack2(acc[p][3]);
                float4 r4;
                r4.x = fmaxf(f0.x + f0.y + bv.x, 0.f);
                r4.y = fmaxf(f1.x + f1.y + bv.y, 0.f);
                r4.z = fmaxf(f2.x + f2.y + bv.z, 0.f);
                r4.w = fmaxf(f3.x + f3.y + bv.w, 0.f);
                *(float4*)(s_sh + (p0 + p) * 132 + l * 4) = r4;
            }
        }
        __syncthreads();

        // C2: sigma partials (4 threads/point, float4)
        {
            const int p = tid & 63, q = tid >> 6;
            const float* sp = s_sh + p * 132 + q * 32;
            const float* wq = w_sig + q * 32;
            float acc = 0.f;
#pragma unroll
            for (int i = 0; i < 8; i++) {
                const float4 sv = *(const float4*)(sp + i * 4);
                const float4 wv = *(const float4*)(wq + i * 4);
                acc = fmaf(sv.x, wv.x, acc); acc = fmaf(sv.y, wv.y, acc);
                acc = fmaf(sv.z, wv.z, acc); acc = fmaf(sv.w, wv.w, acc);
            }
            s_red[q * 64 + p] = acc;
        }
        __syncthreads();
        if (tid < 64) {
            const int p = tid;
            const float t = s_red[p] + s_red[64 + p] + s_red[128 + p] + s_red[192 + p] + b_sig[0];
            const float sg = fmaxf(t, 0.f) + log1pf(expf(-fabsf(t)));  // softplus
            const float sc = logf(sg + 1e-10f) / 0.166667f + s_g[p * 8 + e];
            if (e == 0 || sc > s_bsc[p]) {
                s_bsc[p]  = sc;
                s_bsig[p] = sg;
                s_bexp[p] = (float)e;
            }
        }
        __syncthreads();
    }

    // ---------- C1': recompute winner's shape (per-point expert weights) ----------
    {
        int we[8];
        const float* wpp[8];
#pragma unroll
        for (int p = 0; p < 8; p++) {
            we[p]  = (int)s_bexp[p0 + p];
            wpp[p] = W_sh + we[p] * WDIM * WDIM + l * 4;
        }
        float acc[8][4];
#pragma unroll
        for (int p = 0; p < 8; p++) {
            const float4 bv = *(const float4*)(b_sh + we[p] * WDIM + l * 4);
            acc[p][0] = bv.x; acc[p][1] = bv.y; acc[p][2] = bv.z; acc[p][3] = bv.w;
        }
        const float* yb = s_y + p0 * WDIM;
#pragma unroll 2
        for (int k = 0; k < WDIM; k++) {
#pragma unroll
            for (int p = 0; p < 8; p++) {
                const float4 wv = *(const float4*)(wpp[p] + k * WDIM);
                const float xv = yb[p * WDIM + k];
                acc[p][0] = fmaf(xv, wv.x, acc[p][0]);
                acc[p][1] = fmaf(xv, wv.y, acc[p][1]);
                acc[p][2] = fmaf(xv, wv.z, acc[p][2]);
                acc[p][3] = fmaf(xv, wv.w, acc[p][3]);
            }
        }
#pragma unroll
        for (int p = 0; p < 8; p++) {
            float4 r4;
            r4.x = fmaxf(acc[p][0], 0.f); r4.y = fmaxf(acc[p][1], 0.f);
            r4.z = fmaxf(acc[p][2], 0.f); r4.w = fmaxf(acc[p][3], 0.f);
            *(float4*)(s_sh + (p0 + p) * 132 + l * 4) = r4;
        }
    }
    __syncthreads();

    // ---------- C3': h = relu([shape | vd] @ W_r1[winner] + b_r1[winner]) ----------
    {
        const float* w1p[8];
        float acc[8][2];
#pragma unroll
        for (int p = 0; p < 8; p++) {
            const int we = (int)s_bexp[p0 + p];
            w1p[p] = W_r1 + we * (WDIM + DVV) * HDIM + l * 2;
            const float2 bv = *(const float2*)(b_r1 + we * HDIM + l * 2);
            acc[p][0] = bv.x; acc[p][1] = bv.y;
        }
        const float* sb = s_sh + p0 * 132;
#pragma unroll 2
        for (int k = 0; k < WDIM; k++) {
#pragma unroll
            for (int p = 0; p < 8; p++) {
                const float2 wv = *(const float2*)(w1p[p] + k * HDIM);
                const float xv = sb[p * 132 + k];
                acc[p][0] = fmaf(xv, wv.x, acc[p][0]);
                acc[p][1] = fmaf(xv, wv.y, acc[p][1]);
            }
        }
        const float* vb = s_vd + p0 * 28;
#pragma unroll
        for (int k = 0; k < DVV; k++) {
#pragma unroll
            for (int p = 0; p < 8; p++) {
                const float2 wv = *(const float2*)(w1p[p] + (WDIM + k) * HDIM);
                const float xv = vb[p * 28 + k];
                acc[p][0] = fmaf(xv, wv.x, acc[p][0]);
                acc[p][1] = fmaf(xv, wv.y, acc[p][1]);
            }
        }
#pragma unroll
        for (int p = 0; p < 8; p++) {
            float2 r2;
            r2.x = fmaxf(acc[p][0], 0.f);
            r2.y = fmaxf(acc[p][1], 0.f);
            *(float2*)(s_h + (p0 + p) * 66 + l * 2) = r2;
        }
    }
    __syncthreads();

    // ---------- C4': rgb = sigmoid(h @ W_r2[winner] + b_r2[winner]) → out ----------
    if (tid < 192) {
        const int p = tid % 64, c = tid / 64;
        const int we = (int)s_bexp[p];
        float acc = b_r2[we * 3 + c];
        const float* hp = s_h + p * 66;
        const float* w2 = W_r2 + we * HDIM * 3 + c;
#pragma unroll
        for (int k = 0; k < HDIM; k++) acc = fmaf(hp[k], w2[k * 3], acc);
        if (n0 + p < n)
            out[(n0 + p) * 4 + c] = 1.f / (1.f + expf(-acc));
    }
    if (tid < 64 && n0 + tid < n)
        out[(n0 + tid) * 4 + 3] = s_bsig[tid];
}

extern "C" void kernel_launch(void* const* d_in, const int* in_sizes, int n_in,
                              void* d_out, int out_size) {
    const float* x     = (const float*)d_in[0];
    const float* W_enc = (const float*)d_in[1];
    const float* b_enc = (const float*)d_in[2];
    const float* W_sh  = (const float*)d_in[3];
    const float* b_sh  = (const float*)d_in[4];
    const float* w_sig = (const float*)d_in[5];
    const float* b_sig = (const float*)d_in[6];
    const float* W_r1  = (const float*)d_in[7];
    const float* b_r1  = (const float*)d_in[8];
    const float* W_r2  = (const float*)d_in[9];
    const float* b_r2  = (const float*)d_in[10];
    float* out = (float*)d_out;

    const int n = in_sizes[0] / 6;
    const int blocks = (n + TP - 1) / TP;
    const int smem = SMEM_FLOATS * (int)sizeof(float);

    cudaFuncSetAttribute(nerf_fused, cudaFuncAttributeMaxDynamicSharedMemorySize, smem);
    nerf_fused<<<blocks, NTH, smem>>>(x, W_enc, b_enc, W_sh, b_sh, w_sig, b_sig,
                                      W_r1, b_r1, W_r2, b_r2, out, n);
}

// round 4
// speedup vs baseline: 1.2372x; 1.1035x over previous
#include <cuda_runtime.h>
#include <stdint.h>

#define TP   64
#define NTH  256
#define WDIM 128
#define HDIM 64
#define EXP  8
#define DXX  63
#define DVV  27
#define KK1  78       // padded k-pairs for W_r1 (155 -> 156)

typedef unsigned long long ull;

// ---- pre-packed weight scratch (k-pair interleaved) ----
__device__ float g_Wenc[32 * 128 * 2];           // [kp][c][2]  (k=63 zero-padded)
__device__ float g_Wsh [8 * 64 * 128 * 2];       // [e][kp][c][2]
__device__ float g_Wr1 [8 * KK1 * 64 * 2];       // [e][kp][c][2] (k=155 zero-padded)

// ---- shared memory layout (floats) ----
// U region: s_xyz (first 64*66) overlaid by s_shb [64][128] (xyz dead after Phase B)
#define OFF_U    0
#define OFF_VD   (OFF_U   + 64*128)     // [64][28]
#define OFF_Y    (OFF_VD  + 64*28)      // [64][128]; s_h [64][66] overlays (y dead after expert loop)
#define OFF_SH   (OFF_Y   + 64*128)     // [64][132]
#define OFF_G    (OFF_SH  + 64*132)     // [64][8]
#define OFF_RED  (OFF_G   + 64*8)       // [4][64]
#define OFF_BSC  (OFF_RED + 64*4)
#define OFF_BSIG (OFF_BSC + 64)
#define OFF_BEXP (OFF_BSIG + 64)
#define OFF_UPD  (OFF_BEXP + 64)
#define SMEM_FLOATS (OFF_UPD + 64)      // 27648 floats = 110592 B

__device__ __forceinline__ void ffma2(ull& acc, ull a, ull b) {
    asm("fma.rn.f32x2 %0, %1, %2, %0;" : "+l"(acc) : "l"(a), "l"(b));
}
__device__ __forceinline__ float2 unpack2(ull v) {
    float2 f; asm("mov.b64 {%0, %1}, %2;" : "=f"(f.x), "=f"(f.y) : "l"(v)); return f;
}

// ---- JAX threefry2x32 (20 rounds) ----
__device__ __forceinline__ uint2 tf2x32(unsigned k0, unsigned k1, unsigned x0, unsigned x1) {
    unsigned ks2 = k0 ^ k1 ^ 0x1BD11BDAu;
    x0 += k0; x1 += k1;
#define TFR(r) { x0 += x1; x1 = (x1 << (r)) | (x1 >> (32 - (r))); x1 ^= x0; }
    TFR(13) TFR(15) TFR(26) TFR(6)
    x0 += k1;  x1 += ks2 + 1u;
    TFR(17) TFR(29) TFR(16) TFR(24)
    x0 += ks2; x1 += k0 + 2u;
    TFR(13) TFR(15) TFR(26) TFR(6)
    x0 += k0;  x1 += k1 + 3u;
    TFR(17) TFR(29) TFR(16) TFR(24)
    x0 += k1;  x1 += ks2 + 4u;
    TFR(13) TFR(15) TFR(26) TFR(6)
    x0 += ks2; x1 += k0 + 5u;
#undef TFR
    return make_uint2(x0, x1);
}

// ---- prep: repack weights into k-pair-interleaved layouts ----
__global__ void prep_pack(const float* __restrict__ W_enc,
                          const float* __restrict__ W_sh,
                          const float* __restrict__ W_r1) {
    const int i = blockIdx.x * blockDim.x + threadIdx.x;
    if (i < 32 * 128 * 2) {
        const int j = i & 1, c = (i >> 1) & 127, kp = i >> 8;
        const int k = 2 * kp + j;
        g_Wenc[i] = (k < DXX) ? W_enc[k * 128 + c] : 0.f;
    }
    const int i2 = i - 32 * 128 * 2;
    if (i2 >= 0 && i2 < 8 * 64 * 128 * 2) {
        const int j = i2 & 1, c = (i2 >> 1) & 127, kp = (i2 >> 8) & 63, e = i2 >> 14;
        g_Wsh[i2] = W_sh[e * 16384 + (2 * kp + j) * 128 + c];
    }
    const int i3 = i - (32 * 128 * 2 + 8 * 64 * 128 * 2);
    if (i3 >= 0 && i3 < 8 * KK1 * 64 * 2) {
        const int e = i3 / (KK1 * 64 * 2), r = i3 % (KK1 * 64 * 2);
        const int kp = r >> 7, c = (r >> 1) & 63, j = r & 1;
        const int k = 2 * kp + j;
        g_Wr1[i3] = (k < 155) ? W_r1[e * 155 * 64 + k * 64 + c] : 0.f;
    }
}

__global__ void __launch_bounds__(NTH, 2)
nerf_fused(const float* __restrict__ x,
           const float* __restrict__ b_enc,
           const float* __restrict__ b_sh,
           const float* __restrict__ w_sig, const float* __restrict__ b_sig,
           const float* __restrict__ b_r1,
           const float* __restrict__ W_r2,  const float* __restrict__ b_r2,
           float* __restrict__ out, int n)
{
    extern __shared__ float sm[];
    const int tid = threadIdx.x;
    const int n0  = blockIdx.x * TP;

    float* s_xyz  = sm + OFF_U;      // stride 66 (Phase A/B only)
    float* s_shb  = sm + OFF_U;      // stride 128 (expert loop onward)
    float* s_vd   = sm + OFF_VD;     // stride 28
    float* s_y    = sm + OFF_Y;      // stride 128
    float* s_h    = sm + OFF_Y;      // stride 66 overlay (after expert loop)
    float* s_sh   = sm + OFF_SH;     // stride 132
    float* s_g    = sm + OFF_G;
    float* s_red  = sm + OFF_RED;
    float* s_bsc  = sm + OFF_BSC;
    float* s_bsig = sm + OFF_BSIG;
    float* s_bexp = sm + OFF_BEXP;
    float* s_upd  = sm + OFF_UPD;

    // ---------- Phase A: positional encodings ----------
    if (tid < 192) {
        const int p = tid / 3, c = tid % 3;
        float xc = 0.f, vc = 0.f;
        if (n0 + p < n) {
            xc = x[(n0 + p) * 6 + c];
            vc = x[(n0 + p) * 6 + 3 + c];
        }
        s_xyz[p * 66 + c] = xc;
        float f = 1.f;
#pragma unroll
        for (int i = 0; i < 10; i++) {
            float sv, cv; sincosf(f * xc, &sv, &cv);
            s_xyz[p * 66 + 3  + 3 * i + c] = sv;
            s_xyz[p * 66 + 33 + 3 * i + c] = cv;
            f *= 2.f;
        }
        s_vd[p * 28 + c] = vc;
        f = 1.f;
#pragma unroll
        for (int i = 0; i < 4; i++) {
            float sv, cv; sincosf(f * vc, &sv, &cv);
            s_vd[p * 28 + 3  + 3 * i + c] = sv;
            s_vd[p * 28 + 15 + 3 * i + c] = cv;
            f *= 2.f;
        }
        if (tid < 64) {
            s_xyz[tid * 66 + 63] = 0.f;   // zero pad for k-pair tail (avoid NaN*0)
            s_vd[tid * 28 + 27]  = 0.f;
        }
    }
    // ---------- Phase A2: Gumbel noise (JAX threefry, partitionable) ----------
    for (int idx = tid; idx < TP * EXP; idx += NTH) {
        const int p = idx >> 3;
        const unsigned f = (unsigned)(n0 + p) * 8u + (unsigned)(idx & 7);
        const uint2 r = tf2x32(0u, 42u, 0u, f);
        const unsigned bits = r.x ^ r.y;
        const float u = __uint_as_float((bits >> 9) | 0x3f800000u) - 1.0f;
        s_g[idx] = -logf(-logf(u + 1e-20f) + 1e-20f);
    }
    __syncthreads();

    const int wp = tid >> 5, l = tid & 31, p0 = wp * 8;

    // ---------- Phase B: y = relu(xyz_pe @ W_enc + b_enc), packed weights ----------
    {
        ull acc[8][4];
#pragma unroll
        for (int p = 0; p < 8; p++)
#pragma unroll
            for (int c = 0; c < 4; c++) acc[p][c] = 0ull;
        const float* wb = g_Wenc + l * 8;
        const float* xb = s_xyz + p0 * 66;
#pragma unroll 2
        for (int kp = 0; kp < 32; kp++) {
            const ull* w01 = (const ull*)(wb + kp * 256);
            const ull pc0 = w01[0], pc1 = w01[1], pc2 = w01[2], pc3 = w01[3];
#pragma unroll
            for (int p = 0; p < 8; p++) {
                const ull a = *(const ull*)(xb + p * 66 + 2 * kp);
                ffma2(acc[p][0], a, pc0); ffma2(acc[p][1], a, pc1);
                ffma2(acc[p][2], a, pc2); ffma2(acc[p][3], a, pc3);
            }
        }
        const float4 bv = *(const float4*)(b_enc + l * 4);
#pragma unroll
        for (int p = 0; p < 8; p++) {
            const float2 f0 = unpack2(acc[p][0]), f1 = unpack2(acc[p][1]);
            const float2 f2 = unpack2(acc[p][2]), f3 = unpack2(acc[p][3]);
            float4 r4;
            r4.x = fmaxf(f0.x + f0.y + bv.x, 0.f);
            r4.y = fmaxf(f1.x + f1.y + bv.y, 0.f);
            r4.z = fmaxf(f2.x + f2.y + bv.z, 0.f);
            r4.w = fmaxf(f3.x + f3.y + bv.w, 0.f);
            *(float4*)(s_y + (p0 + p) * WDIM + l * 4) = r4;
        }
    }
    __syncthreads();

    // ---------- Expert loop: shape + sigma + gating; running-best shape copy ----------
    for (int e = 0; e < EXP; e++) {
        // C1: shape = relu(y @ W_sh[e] + b_sh[e]), packed weights, FFMA2
        {
            ull acc[8][4];
#pragma unroll
            for (int p = 0; p < 8; p++)
#pragma unroll
                for (int c = 0; c < 4; c++) acc[p][c] = 0ull;
            const float* wb = g_Wsh + e * 16384 + l * 8;
            const float* yb = s_y + p0 * WDIM;
#pragma unroll 2
            for (int kp = 0; kp < 64; kp++) {
                const ull* w01 = (const ull*)(wb + kp * 256);
                const ull pc0 = w01[0], pc1 = w01[1], pc2 = w01[2], pc3 = w01[3];
#pragma unroll
                for (int p = 0; p < 8; p++) {
                    const ull a = *(const ull*)(yb + p * WDIM + 2 * kp);
                    ffma2(acc[p][0], a, pc0); ffma2(acc[p][1], a, pc1);
                    ffma2(acc[p][2], a, pc2); ffma2(acc[p][3], a, pc3);
                }
            }
            const float4 bv = *(const float4*)(b_sh + e * WDIM + l * 4);
#pragma unroll
            for (int p = 0; p < 8; p++) {
                const float2 f0 = unpack2(acc[p][0]), f1 = unpack2(acc[p][1]);
                const float2 f2 = unpack2(acc[p][2]), f3 = unpack2(acc[p][3]);
                float4 r4;
                r4.x = fmaxf(f0.x + f0.y + bv.x, 0.f);
                r4.y = fmaxf(f1.x + f1.y + bv.y, 0.f);
                r4.z = fmaxf(f2.x + f2.y + bv.z, 0.f);
                r4.w = fmaxf(f3.x + f3.y + bv.w, 0.f);
                *(float4*)(s_sh + (p0 + p) * 132 + l * 4) = r4;
            }
        }
        __syncthreads();

        // C2: sigma partials (4 threads/point)
        {
            const int p = tid & 63, q = tid >> 6;
            const float* sp = s_sh + p * 132 + q * 32;
            const float* wq = w_sig + q * 32;
            float acc = 0.f;
#pragma unroll
            for (int i = 0; i < 8; i++) {
                const float4 sv = *(const float4*)(sp + i * 4);
                const float4 wv = *(const float4*)(wq + i * 4);
                acc = fmaf(sv.x, wv.x, acc); acc = fmaf(sv.y, wv.y, acc);
                acc = fmaf(sv.z, wv.z, acc); acc = fmaf(sv.w, wv.w, acc);
            }
            s_red[q * 64 + p] = acc;
        }
        __syncthreads();
        if (tid < 64) {
            const int p = tid;
            const float t = s_red[p] + s_red[64 + p] + s_red[128 + p] + s_red[192 + p] + b_sig[0];
            const float sg = fmaxf(t, 0.f) + log1pf(expf(-fabsf(t)));  // softplus
            const float sc = logf(sg + 1e-10f) / 0.166667f + s_g[p * 8 + e];
            const bool win = (e == 0) || (sc > s_bsc[p]);
            s_upd[p] = win ? 1.f : 0.f;
            if (win) {
                s_bsc[p]  = sc;
                s_bsig[p] = sg;
                s_bexp[p] = (float)e;
            }
        }
        __syncthreads();

        // copy newly-winning shape rows into s_shb
#pragma unroll
        for (int p = 0; p < 8; p++) {
            if (s_upd[p0 + p] != 0.f)
                *(float4*)(s_shb + (p0 + p) * 128 + l * 4) =
                    *(const float4*)(s_sh + (p0 + p) * 132 + l * 4);
        }
        __syncthreads();
    }

    // ---------- C3': h = relu([shb | vd] @ W_r1[winner] + b_r1[winner]), packed ----------
    {
        const float* w1p[8];
        ull acc[8][2];
#pragma unroll
        for (int p = 0; p < 8; p++) {
            const int we = (int)s_bexp[p0 + p];
            w1p[p] = g_Wr1 + we * (KK1 * 64 * 2) + l * 4;
            acc[p][0] = 0ull; acc[p][1] = 0ull;
        }
        const float* sb = s_shb + p0 * 128;
#pragma unroll 2
        for (int kp = 0; kp < 64; kp++) {
#pragma unroll
            for (int p = 0; p < 8; p++) {
                const float4 w4 = *(const float4*)(w1p[p] + kp * 128);
                const ull a = *(const ull*)(sb + p * 128 + 2 * kp);
                ffma2(acc[p][0], a, *(const ull*)&w4.x);
                ffma2(acc[p][1], a, *(const ull*)&w4.z);
            }
        }
        const float* vb = s_vd + p0 * 28;
#pragma unroll
        for (int kp = 64; kp < KK1; kp++) {
#pragma unroll
            for (int p = 0; p < 8; p++) {
                const float4 w4 = *(const float4*)(w1p[p] + kp * 128);
                const ull a = *(const ull*)(vb + p * 28 + 2 * (kp - 64));
                ffma2(acc[p][0], a, *(const ull*)&w4.x);
                ffma2(acc[p][1], a, *(const ull*)&w4.z);
            }
        }
#pragma unroll
        for (int p = 0; p < 8; p++) {
            const int we = (int)s_bexp[p0 + p];
            const float2 bv = *(const float2*)(b_r1 + we * HDIM + l * 2);
            const float2 f0 = unpack2(acc[p][0]), f1 = unpack2(acc[p][1]);
            float2 r2;
            r2.x = fmaxf(f0.x + f0.y + bv.x, 0.f);
            r2.y = fmaxf(f1.x + f1.y + bv.y, 0.f);
            *(float2*)(s_h + (p0 + p) * 66 + l * 2) = r2;
        }
    }
    __syncthreads();

    // ---------- C4': rgb = sigmoid(h @ W_r2[winner] + b_r2[winner]) → out ----------
    if (tid < 192) {
        const int p = tid % 64, c = tid / 64;
        const int we = (int)s_bexp[p];
        float acc = b_r2[we * 3 + c];
        const float* hp = s_h + p * 66;
        const float* w2 = W_r2 + we * HDIM * 3 + c;
#pragma unroll
        for (int k = 0; k < HDIM; k++) acc = fmaf(hp[k], w2[k * 3], acc);
        if (n0 + p < n)
            out[(n0 + p) * 4 + c] = 1.f / (1.f + expf(-acc));
    }
    if (tid < 64 && n0 + tid < n)
        out[(n0 + tid) * 4 + 3] = s_bsig[tid];
}

extern "C" void kernel_launch(void* const* d_in, const int* in_sizes, int n_in,
                              void* d_out, int out_size) {
    const float* x     = (const float*)d_in[0];
    const float* W_enc = (const float*)d_in[1];
    const float* b_enc = (const float*)d_in[2];
    const float* W_sh  = (const float*)d_in[3];
    const float* b_sh  = (const float*)d_in[4];
    const float* w_sig = (const float*)d_in[5];
    const float* b_sig = (const float*)d_in[6];
    const float* W_r1  = (const float*)d_in[7];
    const float* b_r1  = (const float*)d_in[8];
    const float* W_r2  = (const float*)d_in[9];
    const float* b_r2  = (const float*)d_in[10];
    float* out = (float*)d_out;

    const int n = in_sizes[0] / 6;
    const int blocks = (n + TP - 1) / TP;
    const int smem = SMEM_FLOATS * (int)sizeof(float);

    const int prep_elems = 32*128*2 + 8*64*128*2 + 8*KK1*64*2;
    prep_pack<<<(prep_elems + 255) / 256, 256>>>(W_enc, W_sh, W_r1);

    cudaFuncSetAttribute(nerf_fused, cudaFuncAttributeMaxDynamicSharedMemorySize, smem);
    nerf_fused<<<blocks, NTH, smem>>>(x, b_enc, b_sh, w_sig, b_sig,
                                      b_r1, W_r2, b_r2, out, n);
}